// round 17
// baseline (speedup 1.0000x reference)
#include <cuda_runtime.h>

// EPG / RF-spoiled SPGR, round 17. vs R16 (1235us, fma util 77.8% of the
// 961us op-count floor): occupancy push — 128-thread blocks with
// __launch_bounds__(128,7) reach 7 blocks/SM = 28 warps (vs 24), enabled by
// freeing the nOneP constant pair via sub.rn.f32x2 (75 -> 73 regs).
// Math identical to R16: 4 voxels/warp, 8-lane groups, 8 states/lane
// (4 f32x2 slots), rotating frame, Ỹ = -i*sa*Z, G = c2*D + Ỹ,
// A = E2*e^{-i delta} pre-shift, 1 SHFL per voxel-pulse, lazy truncation
// (only Fp[49] = gl6 slot-a hi killed), constant-memory trig tables.

#define FULLMASK 0xffffffffu
typedef unsigned long long u64;
#define NP 200

__device__    float4 g_tab4[NP];   // {cos d, cos d, sin d, sin d}
__device__    float2 g_spec2[NP];  // {cos 2phi', sin 2phi'}
__constant__  float4 c_tab4[NP];
__constant__  float2 c_spec2[NP];

__global__ void trig_init_kernel() {
    int p = threadIdx.x + blockIdx.x * blockDim.x;
    if (p >= NP) return;
    const float SPOIL = 2.0420352248333655f;  // float32(deg2rad(117))
    float phi = 0.f, inc = 0.f;
    for (int j = 0; j < p; ++j) { inc += SPOIL; phi += inc; }   // phi_p, exact ref order
    float phin = phi + (inc + SPOIL);                            // phi_{p+1}
    float d = phin - phi;                                        // exact subtraction
    float sd, cd;  sincosf(d, &sd, &cd);
    float s2p, c2p; sincosf(2.0f * phin, &s2p, &c2p);
    g_tab4[p]  = make_float4(cd, cd, sd, sd);
    g_spec2[p] = make_float2(c2p, s2p);
}

static __device__ __forceinline__ u64 pk2(float lo, float hi) {
    u64 r; asm("mov.b64 %0, {%1, %2};" : "=l"(r) : "f"(lo), "f"(hi)); return r;
}
static __device__ __forceinline__ void upk2(u64 v, float& lo, float& hi) {
    asm("mov.b64 {%0, %1}, %2;" : "=f"(lo), "=f"(hi) : "l"(v));
}
static __device__ __forceinline__ u64 f2fma(u64 a, u64 b, u64 c) {
    u64 d; asm("fma.rn.f32x2 %0, %1, %2, %3;" : "=l"(d) : "l"(a), "l"(b), "l"(c)); return d;
}
static __device__ __forceinline__ u64 f2mul(u64 a, u64 b) {
    u64 d; asm("mul.rn.f32x2 %0, %1, %2;" : "=l"(d) : "l"(a), "l"(b)); return d;
}
static __device__ __forceinline__ u64 f2add(u64 a, u64 b) {
    u64 d; asm("add.rn.f32x2 %0, %1, %2;" : "=l"(d) : "l"(a), "l"(b)); return d;
}
static __device__ __forceinline__ u64 f2sub(u64 a, u64 b) {
    u64 d; asm("sub.rn.f32x2 %0, %1, %2;" : "=l"(d) : "l"(a), "l"(b)); return d;
}

__global__ void __launch_bounds__(128, 7)
epg_kernel(const float* __restrict__ T1, const float* __restrict__ T2,
           const float* __restrict__ alpha, const float* __restrict__ TR,
           float* __restrict__ out, int n)
{
    const int wid  = (blockIdx.x * blockDim.x + threadIdx.x) >> 5;
    const int lane = threadIdx.x & 31;
    const int gl   = lane & 7;                // lane within 8-lane group
    const int v    = wid * 4 + (lane >> 3);   // this lane's voxel
    const int vc   = v < n ? v : n - 1;       // clamped for loads

    const float TRv = TR[0];
    const float E1  = expf(-TRv / T1[vc]);
    const float E2  = expf(-TRv / T2[vc]);
    const float a   = alpha[vc];
    float sa, ca; sincosf(a, &sa, &ca);
    const float c2   = 0.5f * (1.0f + ca);    // cos^2(a/2)
    const float sah  = 0.5f * sa;
    const float caE1 = ca * E1;
    const float nSS  = -sah * (sa * E1);      // -(sa^2/2)*E1

    const u64 c2P    = pk2(c2, c2);
    const u64 caE1P  = pk2(caE1, caE1);
    const u64 nSSP   = pk2(nSS, nSS);
    const u64 E2P    = pk2(E2, E2);
    const u64 nE2P   = pk2(-E2, -E2);
    const u64 boostP = pk2(gl == 0 ? -2.0f * sah * (1.0f - E1) : 0.f, 0.f);

    // Lazy truncation: Fp[49] = gl 6, slot a, hi word.
    const u64 mK = (gl == 6) ? 0x00000000ffffffffull : ~0ull;

    // State: slots a..d = {k=8gl+0,1}, {+2,3}, {+4,5}, {+6,7}.
    // Ỹ = -i*sa*Z; init Z[0]=1 -> Ỹi[0] = -sa.
    u64 Par = 0, Pai = 0, Pbr = 0, Pbi = 0, Pcr = 0, Pci = 0, Pdr = 0, Pdi = 0;
    u64 Qar = 0, Qai = 0, Qbr = 0, Qbi = 0, Qcr = 0, Qci = 0, Qdr = 0, Qdi = 0;
    u64 Yar = 0, Yai = pk2(gl == 0 ? -2.0f * sah : 0.f, 0.f);
    u64 Ybr = 0, Ybi = 0, Ycr = 0, Yci = 0, Ydr = 0, Ydi = 0;

    #pragma unroll 2
    for (int p = 0; p < NP - 1; ++p) {
        const float4 t = c_tab4[p];                 // {cd,cd,sd,sd} (uniform LDC)
        const u64 cdP = pk2(t.x, t.y);
        const u64 sdP = pk2(t.z, t.w);
        const float2 sp = c_spec2[p];               // {cos 2phi', sin 2phi'}

        // Coefficients (shared by all 4 slots): A = E2 * e^{-i d}
        const u64 cA  = f2mul(E2P, cdP);
        const u64 sA  = f2mul(E2P, sdP);
        const u64 nsA = f2mul(nE2P, sdP);

        // ---- slot a (carries boost in Ỹi) ----
        const u64 Dar = f2sub(Par, Qar);
        const u64 Dai = f2sub(Pai, Qai);
        const u64 Gar = f2fma(c2P, Dar, Yar);
        const u64 Gai = f2fma(c2P, Dai, Yai);
        const u64 nYar = f2fma(caE1P, Yar, f2mul(nSSP, Dar));
        const u64 nYai = f2fma(caE1P, Yai, f2fma(nSSP, Dai, boostP));
        const u64 Fpar = f2add(Qar, Gar);
        const u64 Fpai = f2add(Qai, Gai);
        const u64 Fmar = f2sub(Par, Gar);
        const u64 Fmai = f2sub(Pai, Gai);
        const u64 nPar = f2fma(sA,  Fpai, f2mul(cA, Fpar)) & mK;
        const u64 nPai = f2fma(nsA, Fpar, f2mul(cA, Fpai)) & mK;
        const u64 nQar = f2fma(nsA, Fmai, f2mul(cA, Fmar));
        const u64 nQai = f2fma(sA,  Fmar, f2mul(cA, Fmai));

        // ---- slot b ----
        const u64 Dbr = f2sub(Pbr, Qbr);
        const u64 Dbi = f2sub(Pbi, Qbi);
        const u64 Gbr = f2fma(c2P, Dbr, Ybr);
        const u64 Gbi = f2fma(c2P, Dbi, Ybi);
        const u64 nYbr = f2fma(caE1P, Ybr, f2mul(nSSP, Dbr));
        const u64 nYbi = f2fma(caE1P, Ybi, f2mul(nSSP, Dbi));
        const u64 Fpbr = f2add(Qbr, Gbr);
        const u64 Fpbi = f2add(Qbi, Gbi);
        const u64 Fmbr = f2sub(Pbr, Gbr);
        const u64 Fmbi = f2sub(Pbi, Gbi);
        const u64 nPbr = f2fma(sA,  Fpbi, f2mul(cA, Fpbr));
        const u64 nPbi = f2fma(nsA, Fpbr, f2mul(cA, Fpbi));
        const u64 nQbr = f2fma(nsA, Fmbi, f2mul(cA, Fmbr));
        const u64 nQbi = f2fma(sA,  Fmbr, f2mul(cA, Fmbi));

        // ---- slot c ----
        const u64 Dcr = f2sub(Pcr, Qcr);
        const u64 Dci = f2sub(Pci, Qci);
        const u64 Gcr = f2fma(c2P, Dcr, Ycr);
        const u64 Gci = f2fma(c2P, Dci, Yci);
        const u64 nYcr = f2fma(caE1P, Ycr, f2mul(nSSP, Dcr));
        const u64 nYci = f2fma(caE1P, Yci, f2mul(nSSP, Dci));
        const u64 Fpcr = f2add(Qcr, Gcr);
        const u64 Fpci = f2add(Qci, Gci);
        const u64 Fmcr = f2sub(Pcr, Gcr);
        const u64 Fmci = f2sub(Pci, Gci);
        const u64 nPcr = f2fma(sA,  Fpci, f2mul(cA, Fpcr));
        const u64 nPci = f2fma(nsA, Fpcr, f2mul(cA, Fpci));
        const u64 nQcr = f2fma(nsA, Fmci, f2mul(cA, Fmcr));
        const u64 nQci = f2fma(sA,  Fmcr, f2mul(cA, Fmci));

        // ---- slot d ----
        const u64 Ddr = f2sub(Pdr, Qdr);
        const u64 Ddi = f2sub(Pdi, Qdi);
        const u64 Gdr = f2fma(c2P, Ddr, Ydr);
        const u64 Gdi = f2fma(c2P, Ddi, Ydi);
        const u64 nYdr = f2fma(caE1P, Ydr, f2mul(nSSP, Ddr));
        const u64 nYdi = f2fma(caE1P, Ydi, f2mul(nSSP, Ddi));
        const u64 Fpdr = f2add(Qdr, Gdr);
        const u64 Fpdi = f2add(Qdi, Gdi);
        const u64 Fmdr = f2sub(Pdr, Gdr);
        const u64 Fmdi = f2sub(Pdi, Gdi);
        const u64 nPdr = f2fma(sA,  Fpdi, f2mul(cA, Fpdr));
        const u64 nPdi = f2fma(nsA, Fpdr, f2mul(cA, Fpdi));
        const u64 nQdr = f2fma(nsA, Fmdi, f2mul(cA, Fmdr));
        const u64 nQdi = f2fma(sA,  Fmdr, f2mul(cA, Fmdi));

        // ---- shift ----
        float PalR, PahR, PalI, PahI, PblR, PbhR, PblI, PbhI;
        float PclR, PchR, PclI, PchI, PdlR, PdhR, PdlI, PdhI;
        upk2(nPar, PalR, PahR); upk2(nPai, PalI, PahI);
        upk2(nPbr, PblR, PbhR); upk2(nPbi, PblI, PbhI);
        upk2(nPcr, PclR, PchR); upk2(nPci, PclI, PchI);
        upk2(nPdr, PdlR, PdhR); upk2(nPdi, PdlI, PdhI);
        float QalR, QahR, QalI, QahI, QblR, QbhR, QblI, QbhI;
        float QclR, QchR, QclI, QchI, QdlR, QdhR, QdlI, QdhI;
        upk2(nQar, QalR, QahR); upk2(nQai, QalI, QahI);
        upk2(nQbr, QblR, QbhR); upk2(nQbi, QblI, QbhI);
        upk2(nQcr, QclR, QchR); upk2(nQci, QclI, QchI);
        upk2(nQdr, QdlR, QdhR); upk2(nQdi, QdlI, QdhI);

        float su_r = __shfl_up_sync(FULLMASK, PdhR, 1, 8);
        float su_i = __shfl_up_sync(FULLMASK, PdhI, 1, 8);
        float sd_r = __shfl_down_sync(FULLMASK, QalR, 1, 8);
        float sd_i = __shfl_down_sync(FULLMASK, QalI, 1, 8);
        // gl==7 shfl_down clamp returns own Fm[56] == 0 (induction). OK.

        // gl==0: Fp'[0] = nQ[1] * e^{-2i phi'}  (nQ[1] = own slot-a hi)
        const float spec_r = QahR * sp.x + QahI * sp.y;
        const float spec_i = QahI * sp.x - QahR * sp.y;
        if (gl == 0) { su_r = spec_r; su_i = spec_i; }

        Par = pk2(su_r, PalR);  Pai = pk2(su_i, PalI);
        Pbr = pk2(PahR, PblR);  Pbi = pk2(PahI, PblI);
        Pcr = pk2(PbhR, PclR);  Pci = pk2(PbhI, PclI);
        Pdr = pk2(PchR, PdlR);  Pdi = pk2(PchI, PdlI);
        Qar = pk2(QahR, QblR);  Qai = pk2(QahI, QblI);
        Qbr = pk2(QbhR, QclR);  Qbi = pk2(QbhI, QclI);
        Qcr = pk2(QchR, QdlR);  Qci = pk2(QchI, QdlI);
        Qdr = pk2(QdhR, sd_r);  Qdi = pk2(QdhI, sd_i);
        Yar = nYar; Yai = nYai; Ybr = nYbr; Ybi = nYbi;
        Ycr = nYcr; Yci = nYci; Ydr = nYdr; Ydi = nYdi;
    }

    // Final pulse: signal = |(Q + G)[0]|, G = c2*D + Ỹ (gl==0, slot a, lo)
    {
        float P0r, P0i, Q0r, Q0i, Y0r, Y0i, dum;
        upk2(Par, P0r, dum); upk2(Pai, P0i, dum);
        upk2(Qar, Q0r, dum); upk2(Qai, Q0i, dum);
        upk2(Yar, Y0r, dum); upk2(Yai, Y0i, dum);
        const float D0r = P0r - Q0r;
        const float D0i = P0i - Q0i;
        const float G0r = c2 * D0r + Y0r;
        const float G0i = c2 * D0i + Y0i;
        const float Fp0r = Q0r + G0r;
        const float Fp0i = Q0i + G0i;
        if (gl == 0 && v < n) out[v] = sqrtf(Fp0r * Fp0r + Fp0i * Fp0i);
    }
}

extern "C" void kernel_launch(void* const* d_in, const int* in_sizes, int n_in,
                              void* d_out, int out_size)
{
    const float* T1    = (const float*)d_in[0];
    const float* T2    = (const float*)d_in[1];
    const float* alpha = (const float*)d_in[2];
    const float* TR    = (const float*)d_in[3];
    float* out = (float*)d_out;

    const int n = in_sizes[0];
    trig_init_kernel<<<1, 256>>>();

    void *p_ctab = 0, *p_gtab = 0, *p_cspec = 0, *p_gspec = 0;
    cudaGetSymbolAddress(&p_ctab,  c_tab4);
    cudaGetSymbolAddress(&p_gtab,  g_tab4);
    cudaGetSymbolAddress(&p_cspec, c_spec2);
    cudaGetSymbolAddress(&p_gspec, g_spec2);
    cudaMemcpyAsync(p_ctab,  p_gtab,  sizeof(float4) * NP, cudaMemcpyDeviceToDevice);
    cudaMemcpyAsync(p_cspec, p_gspec, sizeof(float2) * NP, cudaMemcpyDeviceToDevice);

    const int threads = 128;                   // 4 warps = 16 voxels per block
    const int vpb = (threads / 32) * 4;
    const int blocks = (n + vpb - 1) / vpb;
    epg_kernel<<<blocks, threads>>>(T1, T2, alpha, TR, out, n);
}